// round 1
// baseline (speedup 1.0000x reference)
#include <cuda_runtime.h>
#include <math.h>

#define NT 8192      // tokens
#define CI 256       // input channels
#define NE 8         // experts
#define NH 512       // hidden
#define CO 256       // output channels

// ---- scratch (static device globals: no allocation allowed) ----
__device__ int   g_cnt[NE];
__device__ int   g_list[NE * NT];                 // entries: t*2 + slot
__device__ float g_wt[NT * 2];                    // combine weight per (t, slot)
__device__ float g_hid[(size_t)NT * 2 * NH];      // 32 MB
__device__ float g_tmp[(size_t)NT * 2 * CO];      // 16 MB

__global__ void k_zero() {
    if (threadIdx.x < NE) g_cnt[threadIdx.x] = 0;
}

// ---- gating: logits = x@Wg + bg + expert_bias; top-2; sigmoid-normalize ----
__global__ void k_gate(const float* __restrict__ x, const float* __restrict__ Wg,
                       const float* __restrict__ bg, const float* __restrict__ eb) {
    __shared__ float sWg[CI * NE];                // 8 KB
    int tid = threadIdx.x;
    for (int i = tid; i < CI * NE; i += 256) sWg[i] = Wg[i];
    __syncthreads();

    int warp = tid >> 5, lane = tid & 31;
    int t = blockIdx.x * 8 + warp;                // grid = NT/8, exact
    const float* xr = x + (size_t)t * CI;

    float acc[NE];
#pragma unroll
    for (int e = 0; e < NE; ++e) acc[e] = 0.f;
#pragma unroll
    for (int j = 0; j < CI / 32; ++j) {
        int c = lane + 32 * j;
        float xv = xr[c];
        const float* wr = &sWg[c * NE];
#pragma unroll
        for (int e = 0; e < NE; ++e) acc[e] = fmaf(xv, wr[e], acc[e]);
    }
#pragma unroll
    for (int e = 0; e < NE; ++e) {
#pragma unroll
        for (int off = 16; off; off >>= 1)
            acc[e] += __shfl_xor_sync(0xffffffffu, acc[e], off);
    }
    if (lane == 0) {
        float v0 = -1e30f, v1 = -1e30f; int i0 = 0, i1 = 0;
#pragma unroll
        for (int e = 0; e < NE; ++e) {
            float v = acc[e] + bg[e] + eb[e];
            if (v > v0)      { v1 = v0; i1 = i0; v0 = v; i0 = e; }
            else if (v > v1) { v1 = v;  i1 = e; }
        }
        float p0 = 1.f / (1.f + expf(-v0));
        float p1 = 1.f / (1.f + expf(-v1));
        float s  = p0 + p1;
        g_wt[t * 2]     = p0 / s;
        g_wt[t * 2 + 1] = p1 / s;
        int p = atomicAdd(&g_cnt[i0], 1);
        g_list[i0 * NT + p] = t * 2;
        p = atomicAdd(&g_cnt[i1], 1);
        g_list[i1 * NT + p] = t * 2 + 1;
    }
}

// ---- grouped GEMM: per (expert, m-tile, n-tile). BM=BN=128, BK=16, 8x8/thread ----
// PH1: A = x (row = entry>>1), Out = gelu(A@W1[e]+b1) -> g_hid[entry]
// PH2: A = g_hid (row = entry), Out = w * (A@W2[e]+b2) -> g_tmp[entry]
template<int KD, int ND, bool PH1>
__global__ __launch_bounds__(256, 2)
void k_gemm(const float* __restrict__ A_x, const float* __restrict__ W,
            const float* __restrict__ bias) {
    const int e   = blockIdx.z;
    const int cnt = g_cnt[e];
    const int m0  = blockIdx.y * 128;
    if (m0 >= cnt) return;
    const int n0  = blockIdx.x * 128;

    __shared__ float As[16][128];
    __shared__ float Bs[16][128];
    __shared__ int   s_ent[128];
    __shared__ int   s_row[128];

    const int tid = threadIdx.x;
    if (tid < 128) {
        int mm  = m0 + tid;
        int idx = (mm < cnt) ? mm : (cnt - 1);     // clamp for safe gather
        int ent = g_list[e * NT + idx];
        s_ent[tid] = (mm < cnt) ? ent : -1;
        s_row[tid] = PH1 ? (ent >> 1) : ent;
    }
    __syncthreads();

    const float* A_src = PH1 ? A_x : (const float*)g_hid;
    const int am = tid >> 1, aq = tid & 1;                    // A loader: 2 thr/row
    const float* aptr = A_src + (size_t)s_row[am] * KD + aq * 8;
    const int bk = tid >> 4, bq = tid & 15;                   // B loader: 16 thr/row
    const float* bbase = W + ((size_t)e * KD + bk) * ND + n0;

    const int ty = tid >> 4, tx = tid & 15;
    float acc[8][8];
#pragma unroll
    for (int i = 0; i < 8; ++i)
#pragma unroll
        for (int j = 0; j < 8; ++j) acc[i][j] = 0.f;

    for (int kb = 0; kb < KD; kb += 16) {
        float4 a0 = *(const float4*)(aptr + kb);
        float4 a1 = *(const float4*)(aptr + kb + 4);
        const float* br = bbase + (size_t)kb * ND;
        float4 b0 = *(const float4*)(br + bq * 4);
        float4 b1 = *(const float4*)(br + 64 + bq * 4);
        __syncthreads();
        As[aq * 8 + 0][am] = a0.x; As[aq * 8 + 1][am] = a0.y;
        As[aq * 8 + 2][am] = a0.z; As[aq * 8 + 3][am] = a0.w;
        As[aq * 8 + 4][am] = a1.x; As[aq * 8 + 5][am] = a1.y;
        As[aq * 8 + 6][am] = a1.z; As[aq * 8 + 7][am] = a1.w;
        *(float4*)&Bs[bk][bq * 4]      = b0;
        *(float4*)&Bs[bk][64 + bq * 4] = b1;
        __syncthreads();
#pragma unroll
        for (int k = 0; k < 16; ++k) {
            float a[8], b[8];
            *(float4*)(a)     = *(const float4*)&As[k][ty * 8];
            *(float4*)(a + 4) = *(const float4*)&As[k][ty * 8 + 4];
            *(float4*)(b)     = *(const float4*)&Bs[k][tx * 8];
            *(float4*)(b + 4) = *(const float4*)&Bs[k][tx * 8 + 4];
#pragma unroll
            for (int i = 0; i < 8; ++i)
#pragma unroll
                for (int j = 0; j < 8; ++j)
                    acc[i][j] = fmaf(a[i], b[j], acc[i][j]);
        }
    }

    const float* bi = bias + (size_t)e * ND + n0;
    float bv[8];
#pragma unroll
    for (int j = 0; j < 8; ++j) bv[j] = bi[tx * 8 + j];

#pragma unroll
    for (int i = 0; i < 8; ++i) {
        int m = ty * 8 + i;
        int ent = s_ent[m];
        if (ent < 0) continue;
        float o[8];
        if (PH1) {
#pragma unroll
            for (int j = 0; j < 8; ++j) {
                float v = acc[i][j] + bv[j];
                o[j] = 0.5f * v * (1.f + erff(v * 0.70710678118654752f));  // exact GELU
            }
            float* orow = g_hid + (size_t)ent * NH + n0;
            *(float4*)(orow + tx * 8)     = *(float4*)(o);
            *(float4*)(orow + tx * 8 + 4) = *(float4*)(o + 4);
        } else {
            float w = g_wt[ent];
#pragma unroll
            for (int j = 0; j < 8; ++j) o[j] = w * (acc[i][j] + bv[j]);
            float* orow = g_tmp + (size_t)ent * CO + n0;
            *(float4*)(orow + tx * 8)     = *(float4*)(o);
            *(float4*)(orow + tx * 8 + 4) = *(float4*)(o + 4);
        }
    }
}

// ---- combine: out[t] = tmp[2t] + tmp[2t+1] ----
__global__ void k_combine(float* __restrict__ out) {
    int i = blockIdx.x * 256 + threadIdx.x;           // float4 index
    const int tot = NT * CO / 4;
    if (i >= tot) return;
    int t = i / (CO / 4);
    int c = i % (CO / 4);
    const float4* tp = (const float4*)g_tmp;
    float4 u = tp[(size_t)(2 * t)     * (CO / 4) + c];
    float4 v = tp[(size_t)(2 * t + 1) * (CO / 4) + c];
    float4 r; r.x = u.x + v.x; r.y = u.y + v.y; r.z = u.z + v.z; r.w = u.w + v.w;
    ((float4*)out)[i] = r;
}

extern "C" void kernel_launch(void* const* d_in, const int* in_sizes, int n_in,
                              void* d_out, int out_size) {
    const float* x  = (const float*)d_in[0];
    const float* Wg = (const float*)d_in[1];
    const float* bg = (const float*)d_in[2];
    const float* eb = (const float*)d_in[3];
    const float* W1 = (const float*)d_in[4];
    const float* b1 = (const float*)d_in[5];
    const float* W2 = (const float*)d_in[6];
    const float* b2 = (const float*)d_in[7];
    float* out = (float*)d_out;

    k_zero<<<1, 32>>>();
    k_gate<<<NT / 8, 256>>>(x, Wg, bg, eb);

    dim3 g1(NH / 128, NT / 128, NE);   // (4, 64, 8) — m-tiles beyond count early-exit
    k_gemm<CI, NH, true ><<<g1, 256>>>(x, W1, b1);

    dim3 g2(CO / 128, NT / 128, NE);   // (2, 64, 8)
    k_gemm<NH, CO, false><<<g2, 256>>>(x, W2, b2);

    k_combine<<<(NT * CO / 4 + 255) / 256, 256>>>(out);
}

// round 4
// speedup vs baseline: 1.7481x; 1.7481x over previous
#include <cuda_runtime.h>
#include <math.h>
#include <stdint.h>

#define NT 8192      // tokens
#define CI 256       // input channels
#define NE 8         // experts
#define NH 512       // hidden
#define CO 256       // output channels
#define NR (2*NT)    // routed rows (K=2)

// ---------------- scratch (device globals; no allocation allowed) ------------
__device__ int   g_cnt[NE];
__device__ int   g_off[NE];
__device__ int   g_list[NE * NT];
__device__ float g_wt[NR];                       // weight per entry (t*2+slot)
__device__ int   g_rowof[NR];                    // entry -> permuted row
__device__ float g_wtp[NR];                      // weight per permuted row
__device__ float g_xp[(size_t)NR * CI];          // permuted inputs, tf32-rounded
__device__ float g_w1r[(size_t)NE * CI * NH];    // W1 tf32-rounded [E][K][N]
__device__ float g_w2r[(size_t)NE * NH * CO];    // W2 tf32-rounded [E][K][N]
__device__ float g_hid[(size_t)NR * NH];         // hidden, tf32-rounded
__device__ float g_tmp[(size_t)NR * CO];         // weighted expert outputs

// ---------------- helpers ----------------------------------------------------
__device__ __forceinline__ float tf32r(float x) {
    uint32_t y;                                   // tf32 cvt needs .b32 dst
    asm("cvt.rna.tf32.f32 %0, %1;" : "=r"(y) : "f"(x));
    return __uint_as_float(y);
}
__device__ __forceinline__ void cp16(float* dst, const float* src) {
    uint32_t d = (uint32_t)__cvta_generic_to_shared(dst);
    asm volatile("cp.async.cg.shared.global [%0], [%1], 16;" :: "r"(d), "l"(src));
}
__device__ __forceinline__ void cp_commit() {
    asm volatile("cp.async.commit_group;");
}
__device__ __forceinline__ void cp_wait0() {
    asm volatile("cp.async.wait_group 0;");
}
__device__ __forceinline__ void mma_tf32(float* d, const uint32_t* a, const uint32_t* b) {
    asm volatile("mma.sync.aligned.m16n8k8.row.col.f32.tf32.tf32.f32 "
                 "{%0,%1,%2,%3}, {%4,%5,%6,%7}, {%8,%9}, {%0,%1,%2,%3};"
                 : "+f"(d[0]), "+f"(d[1]), "+f"(d[2]), "+f"(d[3])
                 : "r"(a[0]), "r"(a[1]), "r"(a[2]), "r"(a[3]),
                   "r"(b[0]), "r"(b[1]));
}

// ---------------- routing ----------------------------------------------------
__global__ void k_zero() { if (threadIdx.x < NE) g_cnt[threadIdx.x] = 0; }

__global__ void k_gate(const float* __restrict__ x, const float* __restrict__ Wg,
                       const float* __restrict__ bg, const float* __restrict__ eb) {
    __shared__ float sWg[CI * NE];
    int tid = threadIdx.x;
    for (int i = tid; i < CI * NE; i += 256) sWg[i] = Wg[i];
    __syncthreads();
    int warp = tid >> 5, lane = tid & 31;
    int t = blockIdx.x * 8 + warp;
    const float* xr = x + (size_t)t * CI;
    float acc[NE];
#pragma unroll
    for (int e = 0; e < NE; ++e) acc[e] = 0.f;
#pragma unroll
    for (int j = 0; j < CI / 32; ++j) {
        int c = lane + 32 * j;
        float xv = xr[c];
        const float* wr = &sWg[c * NE];
#pragma unroll
        for (int e = 0; e < NE; ++e) acc[e] = fmaf(xv, wr[e], acc[e]);
    }
#pragma unroll
    for (int e = 0; e < NE; ++e)
#pragma unroll
        for (int off = 16; off; off >>= 1)
            acc[e] += __shfl_xor_sync(0xffffffffu, acc[e], off);
    if (lane == 0) {
        float v0 = -1e30f, v1 = -1e30f; int i0 = 0, i1 = 0;
#pragma unroll
        for (int e = 0; e < NE; ++e) {
            float v = acc[e] + bg[e] + eb[e];
            if (v > v0)      { v1 = v0; i1 = i0; v0 = v; i0 = e; }
            else if (v > v1) { v1 = v;  i1 = e; }
        }
        float p0 = 1.f / (1.f + expf(-v0));
        float p1 = 1.f / (1.f + expf(-v1));
        float s  = p0 + p1;
        g_wt[t * 2]     = p0 / s;
        g_wt[t * 2 + 1] = p1 / s;
        int p = atomicAdd(&g_cnt[i0], 1);  g_list[i0 * NT + p] = t * 2;
        p     = atomicAdd(&g_cnt[i1], 1);  g_list[i1 * NT + p] = t * 2 + 1;
    }
}

__global__ void k_sched() {
    if (threadIdx.x == 0) {
        int run = 0;
        for (int e = 0; e < NE; ++e) { g_off[e] = run; run += g_cnt[e]; }
    }
}

// permute routed rows into contiguous per-expert segments, tf32-rounded
__global__ void k_permute(const float* __restrict__ x) {
    int slot = blockIdx.x * 8 + (threadIdx.x >> 5);
    int lane = threadIdx.x & 31;
    int e = slot >> 13, i = slot & (NT - 1);
    if (i >= g_cnt[e]) return;
    int ent = g_list[slot];
    int row = g_off[e] + i;
    int t = ent >> 1;
    const float4* src = (const float4*)(x + (size_t)t * CI);
    float4* dst = (float4*)(g_xp + (size_t)row * CI);
#pragma unroll
    for (int j = lane; j < CI / 4; j += 32) {
        float4 v = src[j];
        v.x = tf32r(v.x); v.y = tf32r(v.y); v.z = tf32r(v.z); v.w = tf32r(v.w);
        dst[j] = v;
    }
    if (lane == 0) {
        g_rowof[ent] = row;
        g_wtp[row]   = g_wt[ent];
    }
}

// pre-round both weight tensors to tf32 (RNA) in original [E][K][N] layout
__global__ void k_roundw(const float* __restrict__ w1, const float* __restrict__ w2) {
    int i = blockIdx.x * 256 + threadIdx.x;            // float4 index
    const int n1 = NE * CI * NH / 4;
    const int n2 = NE * NH * CO / 4;
    if (i < n1) {
        float4 v = ((const float4*)w1)[i];
        v.x = tf32r(v.x); v.y = tf32r(v.y); v.z = tf32r(v.z); v.w = tf32r(v.w);
        ((float4*)g_w1r)[i] = v;
    } else if (i < n1 + n2) {
        int j = i - n1;
        float4 v = ((const float4*)w2)[j];
        v.x = tf32r(v.x); v.y = tf32r(v.y); v.z = tf32r(v.z); v.w = tf32r(v.w);
        ((float4*)g_w2r)[j] = v;
    }
}

// ---------------- HMMA grouped GEMM ------------------------------------------
// BM=128, BN=128, BK=32; 256 thr = 8 warps (2x4), warp tile 64x32 (4x4 m16n8k8)
#define BM 128
#define BN 128
#define BK 32
#define LDA 36                       // pad: (m*36+k)%32 = (4m+k)%32 conflict-free
#define LDB 132                      // pad: (k*132+n)%32 = (4k+n)%32 conflict-free
#define A_ST (BM * LDA)              // 4608 floats
#define B_ST (BK * LDB)              // 4224 floats
#define STG_FL (A_ST + B_ST)         // 8832 floats
#define SMEM_SZ (2 * STG_FL * 4)     // 70656 bytes

template<int KD, int ND, bool PH1>
__global__ __launch_bounds__(256, 1)
void k_mma(const float* __restrict__ bias) {
    extern __shared__ float sm[];
    const int e   = blockIdx.z;
    const int cnt = g_cnt[e];
    const int m0  = blockIdx.y * BM;
    if (m0 >= cnt) return;
    const int base = g_off[e];
    const int n0   = blockIdx.x * BN;
    const int tid  = threadIdx.x;
    const int lane = tid & 31;
    const int w    = tid >> 5;
    const int wm   = w >> 2, wn = w & 3;

    const float* Asrc = PH1 ? g_xp : g_hid;
    const float* Bsrc = (PH1 ? g_w1r : g_w2r) + (size_t)e * KD * ND;

    auto load_stage = [&](int kb, int buf) {
        float* as = sm + buf * STG_FL;
        float* bs = as + A_ST;
        const int k0 = kb * BK;
#pragma unroll
        for (int c = 0; c < 4; ++c) {                  // A: 128 x 32 fl
            int idx = tid + c * 256;
            int r = idx >> 3, q = idx & 7;
            int rr = m0 + r; rr = rr < cnt ? rr : cnt - 1;
            cp16(as + r * LDA + q * 4,
                 Asrc + (size_t)(base + rr) * KD + k0 + q * 4);
        }
#pragma unroll
        for (int c = 0; c < 4; ++c) {                  // B: 32 x 128 fl
            int idx = tid + c * 256;
            int k = idx >> 5, q = idx & 31;
            cp16(bs + k * LDB + q * 4,
                 Bsrc + (size_t)(k0 + k) * ND + n0 + q * 4);
        }
        cp_commit();
    };

    float acc[4][4][4];
#pragma unroll
    for (int mt = 0; mt < 4; ++mt)
#pragma unroll
        for (int nt = 0; nt < 4; ++nt)
#pragma unroll
            for (int j = 0; j < 4; ++j) acc[mt][nt][j] = 0.f;

    const int NK = KD / BK;
    load_stage(0, 0);
    for (int kb = 0; kb < NK; ++kb) {
        const int buf = kb & 1;
        cp_wait0();
        __syncthreads();
        if (kb + 1 < NK) load_stage(kb + 1, buf ^ 1);
        const float* as = sm + buf * STG_FL;
        const float* bs = as + A_ST;
        const float* pA = as + (wm * 64 + (lane >> 2)) * LDA + (lane & 3);
        const float* pB = bs + (lane & 3) * LDB + wn * 32 + (lane >> 2);
#pragma unroll
        for (int ks = 0; ks < 4; ++ks) {
            uint32_t af[4][4], bf[4][2];
#pragma unroll
            for (int mt = 0; mt < 4; ++mt) {
                af[mt][0] = __float_as_uint(pA[(mt * 16)     * LDA + ks * 8]);
                af[mt][1] = __float_as_uint(pA[(mt * 16 + 8) * LDA + ks * 8]);
                af[mt][2] = __float_as_uint(pA[(mt * 16)     * LDA + ks * 8 + 4]);
                af[mt][3] = __float_as_uint(pA[(mt * 16 + 8) * LDA + ks * 8 + 4]);
            }
#pragma unroll
            for (int nt = 0; nt < 4; ++nt) {
                bf[nt][0] = __float_as_uint(pB[(ks * 8)     * LDB + nt * 8]);
                bf[nt][1] = __float_as_uint(pB[(ks * 8 + 4) * LDB + nt * 8]);
            }
#pragma unroll
            for (int mt = 0; mt < 4; ++mt)
#pragma unroll
                for (int nt = 0; nt < 4; ++nt)
                    mma_tf32(acc[mt][nt], af[mt], bf[nt]);
        }
        __syncthreads();
    }

    // ---- epilogue straight from registers ----
    const float* bp = bias + (size_t)e * ND + n0;
#pragma unroll
    for (int mt = 0; mt < 4; ++mt) {
        const int lr0 = wm * 64 + mt * 16 + (lane >> 2);
#pragma unroll
        for (int h = 0; h < 2; ++h) {
            const int lr = lr0 + h * 8;
            if (m0 + lr >= cnt) continue;
            const int grow = base + m0 + lr;
            const float wt = PH1 ? 0.f : g_wtp[grow];
#pragma unroll
            for (int nt = 0; nt < 4; ++nt) {
                const int col = wn * 32 + nt * 8 + (lane & 3) * 2;
                float v0 = acc[mt][nt][h * 2 + 0] + bp[col];
                float v1 = acc[mt][nt][h * 2 + 1] + bp[col + 1];
                if (PH1) {
                    v0 = tf32r(0.5f * v0 * (1.f + erff(v0 * 0.70710678118654752f)));
                    v1 = tf32r(0.5f * v1 * (1.f + erff(v1 * 0.70710678118654752f)));
                    float2 o = make_float2(v0, v1);
                    *(float2*)&g_hid[(size_t)grow * NH + n0 + col] = o;
                } else {
                    float2 o = make_float2(wt * v0, wt * v1);
                    *(float2*)&g_tmp[(size_t)grow * CO + n0 + col] = o;
                }
            }
        }
    }
}

// ---------------- combine ----------------------------------------------------
__global__ void k_combine(float* __restrict__ out) {
    int i = blockIdx.x * 256 + threadIdx.x;
    const int tot = NT * CO / 4;
    if (i >= tot) return;
    int t = i / (CO / 4), c = i % (CO / 4);
    int r0 = g_rowof[2 * t], r1 = g_rowof[2 * t + 1];
    const float4* tp = (const float4*)g_tmp;
    float4 u = tp[(size_t)r0 * (CO / 4) + c];
    float4 v = tp[(size_t)r1 * (CO / 4) + c];
    float4 r; r.x = u.x + v.x; r.y = u.y + v.y; r.z = u.z + v.z; r.w = u.w + v.w;
    ((float4*)out)[i] = r;
}

// ---------------- launch -----------------------------------------------------
extern "C" void kernel_launch(void* const* d_in, const int* in_sizes, int n_in,
                              void* d_out, int out_size) {
    const float* x  = (const float*)d_in[0];
    const float* Wg = (const float*)d_in[1];
    const float* bg = (const float*)d_in[2];
    const float* eb = (const float*)d_in[3];
    const float* W1 = (const float*)d_in[4];
    const float* b1 = (const float*)d_in[5];
    const float* W2 = (const float*)d_in[6];
    const float* b2 = (const float*)d_in[7];
    float* out = (float*)d_out;

    cudaFuncSetAttribute(k_mma<CI, NH, true >, cudaFuncAttributeMaxDynamicSharedMemorySize, SMEM_SZ);
    cudaFuncSetAttribute(k_mma<NH, CO, false>, cudaFuncAttributeMaxDynamicSharedMemorySize, SMEM_SZ);

    k_zero<<<1, 32>>>();
    k_gate<<<NT / 8, 256>>>(x, Wg, bg, eb);
    k_sched<<<1, 32>>>();
    k_permute<<<NE * NT / 8, 256>>>(x);
    k_roundw<<<(NE * CI * NH / 4 + NE * NH * CO / 4 + 255) / 256, 256>>>(W1, W2);

    k_mma<CI, NH, true ><<<dim3(NH / 128, 64, NE), 256, SMEM_SZ>>>(b1);
    k_mma<NH, CO, false><<<dim3(CO / 128, 64, NE), 256, SMEM_SZ>>>(b2);

    k_combine<<<(NT * CO / 4 + 255) / 256, 256>>>(out);
}

// round 5
// speedup vs baseline: 1.9424x; 1.1111x over previous
#include <cuda_runtime.h>
#include <math.h>
#include <stdint.h>

#define NT 8192      // tokens
#define CI 256       // input channels
#define NE 8         // experts
#define NH 512       // hidden
#define CO 256       // output channels
#define NR (2*NT)    // routed rows (K=2)

// ---------------- scratch (device globals; no allocation allowed) ------------
__device__ int   g_cnt[NE];
__device__ int   g_off[NE];
__device__ int   g_list[NE * NT];
__device__ float g_wt[NR];                       // weight per entry (t*2+slot)
__device__ int   g_rowof[NR];                    // entry -> permuted row
__device__ float g_wtp[NR];                      // weight per permuted row
__device__ float g_xp[(size_t)NR * CI];          // permuted inputs, tf32-rounded
__device__ float g_w1r[(size_t)NE * CI * NH];    // W1 tf32-rounded [E][K][N]
__device__ float g_w2r[(size_t)NE * NH * CO];    // W2 tf32-rounded [E][K][N]
__device__ float g_hid[(size_t)NR * NH];         // hidden, tf32-rounded
__device__ float g_tmp[(size_t)NR * CO];         // weighted expert outputs

// ---------------- helpers ----------------------------------------------------
__device__ __forceinline__ float tf32r(float x) {
    uint32_t y;
    asm("cvt.rna.tf32.f32 %0, %1;" : "=r"(y) : "f"(x));
    return __uint_as_float(y);
}
__device__ __forceinline__ void cp16(float* dst, const float* src) {
    uint32_t d = (uint32_t)__cvta_generic_to_shared(dst);
    asm volatile("cp.async.cg.shared.global [%0], [%1], 16;" :: "r"(d), "l"(src));
}
__device__ __forceinline__ void cp_commit() {
    asm volatile("cp.async.commit_group;");
}
__device__ __forceinline__ void cp_wait1() {
    asm volatile("cp.async.wait_group 1;");
}
__device__ __forceinline__ void mma_tf32(float* d, const uint32_t* a, const uint32_t* b) {
    asm volatile("mma.sync.aligned.m16n8k8.row.col.f32.tf32.tf32.f32 "
                 "{%0,%1,%2,%3}, {%4,%5,%6,%7}, {%8,%9}, {%0,%1,%2,%3};"
                 : "+f"(d[0]), "+f"(d[1]), "+f"(d[2]), "+f"(d[3])
                 : "r"(a[0]), "r"(a[1]), "r"(a[2]), "r"(a[3]),
                   "r"(b[0]), "r"(b[1]));
}

// ---------------- routing ----------------------------------------------------
__global__ void k_zero() { if (threadIdx.x < NE) g_cnt[threadIdx.x] = 0; }

__global__ void k_gate(const float* __restrict__ x, const float* __restrict__ Wg,
                       const float* __restrict__ bg, const float* __restrict__ eb) {
    __shared__ float sWg[CI * NE];
    int tid = threadIdx.x;
    for (int i = tid; i < CI * NE; i += 256) sWg[i] = Wg[i];
    __syncthreads();
    int warp = tid >> 5, lane = tid & 31;
    int t = blockIdx.x * 8 + warp;
    const float* xr = x + (size_t)t * CI;
    float acc[NE];
#pragma unroll
    for (int e = 0; e < NE; ++e) acc[e] = 0.f;
#pragma unroll
    for (int j = 0; j < CI / 32; ++j) {
        int c = lane + 32 * j;
        float xv = xr[c];
        const float* wr = &sWg[c * NE];
#pragma unroll
        for (int e = 0; e < NE; ++e) acc[e] = fmaf(xv, wr[e], acc[e]);
    }
#pragma unroll
    for (int e = 0; e < NE; ++e)
#pragma unroll
        for (int off = 16; off; off >>= 1)
            acc[e] += __shfl_xor_sync(0xffffffffu, acc[e], off);
    if (lane == 0) {
        float v0 = -1e30f, v1 = -1e30f; int i0 = 0, i1 = 0;
#pragma unroll
        for (int e = 0; e < NE; ++e) {
            float v = acc[e] + bg[e] + eb[e];
            if (v > v0)      { v1 = v0; i1 = i0; v0 = v; i0 = e; }
            else if (v > v1) { v1 = v;  i1 = e; }
        }
        float p0 = 1.f / (1.f + expf(-v0));
        float p1 = 1.f / (1.f + expf(-v1));
        float s  = p0 + p1;
        g_wt[t * 2]     = p0 / s;
        g_wt[t * 2 + 1] = p1 / s;
        int p = atomicAdd(&g_cnt[i0], 1);  g_list[i0 * NT + p] = t * 2;
        p     = atomicAdd(&g_cnt[i1], 1);  g_list[i1 * NT + p] = t * 2 + 1;
    }
}

__global__ void k_sched() {
    if (threadIdx.x == 0) {
        int run = 0;
        for (int e = 0; e < NE; ++e) { g_off[e] = run; run += g_cnt[e]; }
    }
}

// permute routed rows into contiguous per-expert segments, tf32-rounded
__global__ void k_permute(const float* __restrict__ x) {
    int slot = blockIdx.x * 8 + (threadIdx.x >> 5);
    int lane = threadIdx.x & 31;
    int e = slot >> 13, i = slot & (NT - 1);
    if (i >= g_cnt[e]) return;
    int ent = g_list[slot];
    int row = g_off[e] + i;
    int t = ent >> 1;
    const float4* src = (const float4*)(x + (size_t)t * CI);
    float4* dst = (float4*)(g_xp + (size_t)row * CI);
#pragma unroll
    for (int j = lane; j < CI / 4; j += 32) {
        float4 v = src[j];
        v.x = tf32r(v.x); v.y = tf32r(v.y); v.z = tf32r(v.z); v.w = tf32r(v.w);
        dst[j] = v;
    }
    if (lane == 0) {
        g_rowof[ent] = row;
        g_wtp[row]   = g_wt[ent];
    }
}

// pre-round both weight tensors to tf32 (RNA) in original [E][K][N] layout
__global__ void k_roundw(const float* __restrict__ w1, const float* __restrict__ w2) {
    int i = blockIdx.x * 256 + threadIdx.x;            // float4 index
    const int n1 = NE * CI * NH / 4;
    const int n2 = NE * NH * CO / 4;
    if (i < n1) {
        float4 v = ((const float4*)w1)[i];
        v.x = tf32r(v.x); v.y = tf32r(v.y); v.z = tf32r(v.z); v.w = tf32r(v.w);
        ((float4*)g_w1r)[i] = v;
    } else if (i < n1 + n2) {
        int j = i - n1;
        float4 v = ((const float4*)w2)[j];
        v.x = tf32r(v.x); v.y = tf32r(v.y); v.z = tf32r(v.z); v.w = tf32r(v.w);
        ((float4*)g_w2r)[j] = v;
    }
}

// ---------------- HMMA grouped GEMM ------------------------------------------
// BM=128, BN=128, BK=32; 256 thr = 8 warps (2x4), warp tile 64x32 (4x4 m16n8k8)
// 2 CTAs/SM; prefetch-depth-2 cp.async pipeline with wait_group 1.
#define BM 128
#define BN 128
#define BK 32
#define LDA 36                       // pad: (m*36+k)%32 = (4m+k)%32 conflict-free
#define LDB 132                      // pad: (k*132+n)%32 = (4k+n)%32 conflict-free
#define A_ST (BM * LDA)              // 4608 floats
#define B_ST (BK * LDB)              // 4224 floats
#define STG_FL (A_ST + B_ST)         // 8832 floats
#define SMEM_SZ (2 * STG_FL * 4)     // 70656 bytes -> 2 CTAs/SM (141KB < 228KB)

template<int KD, int ND, bool PH1>
__global__ __launch_bounds__(256, 2)
void k_mma(const float* __restrict__ bias) {
    extern __shared__ float sm[];
    const int e   = blockIdx.z;
    const int cnt = g_cnt[e];
    const int m0  = blockIdx.y * BM;
    if (m0 >= cnt) return;
    const int base = g_off[e];
    const int n0   = blockIdx.x * BN;
    const int tid  = threadIdx.x;
    const int lane = tid & 31;
    const int w    = tid >> 5;
    const int wm   = w >> 2, wn = w & 3;

    const float* Asrc = PH1 ? g_xp : g_hid;
    const float* Bsrc = (PH1 ? g_w1r : g_w2r) + (size_t)e * KD * ND;

    auto load_stage = [&](int kb, int buf) {
        float* as = sm + buf * STG_FL;
        float* bs = as + A_ST;
        const int k0 = kb * BK;
#pragma unroll
        for (int c = 0; c < 4; ++c) {                  // A: 128 x 32 fl
            int idx = tid + c * 256;
            int r = idx >> 3, q = idx & 7;
            int rr = m0 + r; rr = rr < cnt ? rr : cnt - 1;
            cp16(as + r * LDA + q * 4,
                 Asrc + (size_t)(base + rr) * KD + k0 + q * 4);
        }
#pragma unroll
        for (int c = 0; c < 4; ++c) {                  // B: 32 x 128 fl
            int idx = tid + c * 256;
            int k = idx >> 5, q = idx & 31;
            cp16(bs + k * LDB + q * 4,
                 Bsrc + (size_t)(k0 + k) * ND + n0 + q * 4);
        }
        cp_commit();
    };

    float acc[4][4][4];
#pragma unroll
    for (int mt = 0; mt < 4; ++mt)
#pragma unroll
        for (int nt = 0; nt < 4; ++nt)
#pragma unroll
            for (int j = 0; j < 4; ++j) acc[mt][nt][j] = 0.f;

    const int NK = KD / BK;
    load_stage(0, 0);
    load_stage(1, 1);
    for (int kb = 0; kb < NK; ++kb) {
        const int buf = kb & 1;
        cp_wait1();                                    // stage kb arrived (kb+1 in flight)
        __syncthreads();
        const float* as = sm + buf * STG_FL;
        const float* bs = as + A_ST;
        const float* pA = as + (wm * 64 + (lane >> 2)) * LDA + (lane & 3);
        const float* pB = bs + (lane & 3) * LDB + wn * 32 + (lane >> 2);
#pragma unroll
        for (int ks = 0; ks < 4; ++ks) {
            uint32_t af[4][4], bf[4][2];
#pragma unroll
            for (int mt = 0; mt < 4; ++mt) {
                af[mt][0] = __float_as_uint(pA[(mt * 16)     * LDA + ks * 8]);
                af[mt][1] = __float_as_uint(pA[(mt * 16 + 8) * LDA + ks * 8]);
                af[mt][2] = __float_as_uint(pA[(mt * 16)     * LDA + ks * 8 + 4]);
                af[mt][3] = __float_as_uint(pA[(mt * 16 + 8) * LDA + ks * 8 + 4]);
            }
#pragma unroll
            for (int nt = 0; nt < 4; ++nt) {
                bf[nt][0] = __float_as_uint(pB[(ks * 8)     * LDB + nt * 8]);
                bf[nt][1] = __float_as_uint(pB[(ks * 8 + 4) * LDB + nt * 8]);
            }
#pragma unroll
            for (int mt = 0; mt < 4; ++mt)
#pragma unroll
                for (int nt = 0; nt < 4; ++nt)
                    mma_tf32(acc[mt][nt], af[mt], bf[nt]);
        }
        __syncthreads();
        if (kb + 2 < NK) load_stage(kb + 2, buf);      // refill just-freed buffer
    }

    // ---- epilogue straight from registers ----
    const float* bp = bias + (size_t)e * ND + n0;
#pragma unroll
    for (int mt = 0; mt < 4; ++mt) {
        const int lr0 = wm * 64 + mt * 16 + (lane >> 2);
#pragma unroll
        for (int h = 0; h < 2; ++h) {
            const int lr = lr0 + h * 8;
            if (m0 + lr >= cnt) continue;
            const int grow = base + m0 + lr;
            const float wt = PH1 ? 0.f : g_wtp[grow];
#pragma unroll
            for (int nt = 0; nt < 4; ++nt) {
                const int col = wn * 32 + nt * 8 + (lane & 3) * 2;
                float v0 = acc[mt][nt][h * 2 + 0] + bp[col];
                float v1 = acc[mt][nt][h * 2 + 1] + bp[col + 1];
                if (PH1) {
                    v0 = tf32r(0.5f * v0 * (1.f + erff(v0 * 0.70710678118654752f)));
                    v1 = tf32r(0.5f * v1 * (1.f + erff(v1 * 0.70710678118654752f)));
                    float2 o = make_float2(v0, v1);
                    *(float2*)&g_hid[(size_t)grow * NH + n0 + col] = o;
                } else {
                    float2 o = make_float2(wt * v0, wt * v1);
                    *(float2*)&g_tmp[(size_t)grow * CO + n0 + col] = o;
                }
            }
        }
    }
}

// ---------------- combine ----------------------------------------------------
__global__ void k_combine(float* __restrict__ out) {
    int i = blockIdx.x * 256 + threadIdx.x;
    const int tot = NT * CO / 4;
    if (i >= tot) return;
    int t = i / (CO / 4), c = i % (CO / 4);
    int r0 = g_rowof[2 * t], r1 = g_rowof[2 * t + 1];
    const float4* tp = (const float4*)g_tmp;
    float4 u = tp[(size_t)r0 * (CO / 4) + c];
    float4 v = tp[(size_t)r1 * (CO / 4) + c];
    float4 r; r.x = u.x + v.x; r.y = u.y + v.y; r.z = u.z + v.z; r.w = u.w + v.w;
    ((float4*)out)[i] = r;
}

// ---------------- launch -----------------------------------------------------
extern "C" void kernel_launch(void* const* d_in, const int* in_sizes, int n_in,
                              void* d_out, int out_size) {
    const float* x  = (const float*)d_in[0];
    const float* Wg = (const float*)d_in[1];
    const float* bg = (const float*)d_in[2];
    const float* eb = (const float*)d_in[3];
    const float* W1 = (const float*)d_in[4];
    const float* b1 = (const float*)d_in[5];
    const float* W2 = (const float*)d_in[6];
    const float* b2 = (const float*)d_in[7];
    float* out = (float*)d_out;

    cudaFuncSetAttribute(k_mma<CI, NH, true >, cudaFuncAttributeMaxDynamicSharedMemorySize, SMEM_SZ);
    cudaFuncSetAttribute(k_mma<NH, CO, false>, cudaFuncAttributeMaxDynamicSharedMemorySize, SMEM_SZ);

    k_zero<<<1, 32>>>();
    k_gate<<<NT / 8, 256>>>(x, Wg, bg, eb);
    k_sched<<<1, 32>>>();
    k_permute<<<NE * NT / 8, 256>>>(x);
    k_roundw<<<(NE * CI * NH / 4 + NE * NH * CO / 4 + 255) / 256, 256>>>(W1, W2);

    k_mma<CI, NH, true ><<<dim3(NH / 128, 64, NE), 256, SMEM_SZ>>>(b1);
    k_mma<NH, CO, false><<<dim3(CO / 128, 64, NE), 256, SMEM_SZ>>>(b2);

    k_combine<<<(NT * CO / 4 + 255) / 256, 256>>>(out);
}

// round 16
// speedup vs baseline: 2.0379x; 1.0492x over previous
#include <cuda_runtime.h>
#include <math.h>
#include <stdint.h>

#define NT 8192      // tokens
#define CI 256       // input channels
#define NE 8         // experts
#define NH 512       // hidden
#define CO 256       // output channels
#define NR (2*NT)    // routed rows (K=2)

// ---------------- scratch (device globals; no allocation allowed) ------------
__device__ int   g_cnt[NE];
__device__ int   g_off[NE];
__device__ int   g_list[NE * NT];
__device__ float g_wt[NR];                       // weight per entry (t*2+slot)
__device__ int   g_rowof[NR];                    // entry -> permuted row
__device__ float g_wtp[NR];                      // weight per permuted row
__device__ float g_xp[(size_t)NR * CI];          // permuted inputs, tf32-rounded
__device__ float g_w1r[(size_t)NE * CI * NH];    // W1 tf32-rounded [E][K][N]
__device__ float g_w2r[(size_t)NE * NH * CO];    // W2 tf32-rounded [E][K][N]
__device__ float g_hid[(size_t)NR * NH];         // hidden, tf32-rounded
__device__ float g_tmp[(size_t)NR * CO];         // weighted expert outputs

// ---------------- helpers ----------------------------------------------------
__device__ __forceinline__ float tf32r(float x) {
    uint32_t y;
    asm("cvt.rna.tf32.f32 %0, %1;" : "=r"(y) : "f"(x));
    return __uint_as_float(y);
}
__device__ __forceinline__ void cp16(float* dst, const float* src) {
    uint32_t d = (uint32_t)__cvta_generic_to_shared(dst);
    asm volatile("cp.async.cg.shared.global [%0], [%1], 16;" :: "r"(d), "l"(src));
}
__device__ __forceinline__ void cp_commit() {
    asm volatile("cp.async.commit_group;");
}
__device__ __forceinline__ void cp_wait1() {
    asm volatile("cp.async.wait_group 1;");
}
__device__ __forceinline__ void mma_tf32(float* d, const uint32_t* a, const uint32_t* b) {
    asm volatile("mma.sync.aligned.m16n8k8.row.col.f32.tf32.tf32.f32 "
                 "{%0,%1,%2,%3}, {%4,%5,%6,%7}, {%8,%9}, {%0,%1,%2,%3};"
                 : "+f"(d[0]), "+f"(d[1]), "+f"(d[2]), "+f"(d[3])
                 : "r"(a[0]), "r"(a[1]), "r"(a[2]), "r"(a[3]),
                   "r"(b[0]), "r"(b[1]));
}

// ---------------- routing ----------------------------------------------------
__global__ void k_zero() { if (threadIdx.x < NE) g_cnt[threadIdx.x] = 0; }

// fused: blocks [0, NT/8) gate tokens; blocks [NT/8, ...) tf32-round W1/W2
__global__ void k_gate_roundw(const float* __restrict__ x, const float* __restrict__ Wg,
                              const float* __restrict__ bg, const float* __restrict__ eb,
                              const float* __restrict__ w1, const float* __restrict__ w2) {
    __shared__ float sWg[CI * NE];
    int tid = threadIdx.x;

    if (blockIdx.x >= NT / 8) {                    // ---- weight rounding part ----
        int i = (blockIdx.x - NT / 8) * 256 + tid; // float4 index
        const int n1 = NE * CI * NH / 4;
        const int n2 = NE * NH * CO / 4;
        if (i < n1) {
            float4 v = ((const float4*)w1)[i];
            v.x = tf32r(v.x); v.y = tf32r(v.y); v.z = tf32r(v.z); v.w = tf32r(v.w);
            ((float4*)g_w1r)[i] = v;
        } else if (i < n1 + n2) {
            int j = i - n1;
            float4 v = ((const float4*)w2)[j];
            v.x = tf32r(v.x); v.y = tf32r(v.y); v.z = tf32r(v.z); v.w = tf32r(v.w);
            ((float4*)g_w2r)[j] = v;
        }
        return;
    }

    // ---- gating part ----
    for (int i = tid; i < CI * NE; i += 256) sWg[i] = Wg[i];
    __syncthreads();
    int warp = tid >> 5, lane = tid & 31;
    int t = blockIdx.x * 8 + warp;
    const float* xr = x + (size_t)t * CI;
    float acc[NE];
#pragma unroll
    for (int e = 0; e < NE; ++e) acc[e] = 0.f;
#pragma unroll
    for (int j = 0; j < CI / 32; ++j) {
        int c = lane + 32 * j;
        float xv = xr[c];
        const float* wr = &sWg[c * NE];
#pragma unroll
        for (int e = 0; e < NE; ++e) acc[e] = fmaf(xv, wr[e], acc[e]);
    }
#pragma unroll
    for (int e = 0; e < NE; ++e)
#pragma unroll
        for (int off = 16; off; off >>= 1)
            acc[e] += __shfl_xor_sync(0xffffffffu, acc[e], off);
    if (lane == 0) {
        float v0 = -1e30f, v1 = -1e30f; int i0 = 0, i1 = 0;
#pragma unroll
        for (int e = 0; e < NE; ++e) {
            float v = acc[e] + bg[e] + eb[e];
            if (v > v0)      { v1 = v0; i1 = i0; v0 = v; i0 = e; }
            else if (v > v1) { v1 = v;  i1 = e; }
        }
        float p0 = 1.f / (1.f + expf(-v0));
        float p1 = 1.f / (1.f + expf(-v1));
        float s  = p0 + p1;
        g_wt[t * 2]     = p0 / s;
        g_wt[t * 2 + 1] = p1 / s;
        int p = atomicAdd(&g_cnt[i0], 1);  g_list[i0 * NT + p] = t * 2;
        p     = atomicAdd(&g_cnt[i1], 1);  g_list[i1 * NT + p] = t * 2 + 1;
    }
}

__global__ void k_sched() {
    if (threadIdx.x == 0) {
        int run = 0;
        for (int e = 0; e < NE; ++e) { g_off[e] = run; run += g_cnt[e]; }
    }
}

// permute routed rows into contiguous per-expert segments, tf32-rounded
__global__ void k_permute(const float* __restrict__ x) {
    int slot = blockIdx.x * 8 + (threadIdx.x >> 5);
    int lane = threadIdx.x & 31;
    int e = slot >> 13, i = slot & (NT - 1);
    if (i >= g_cnt[e]) return;
    int ent = g_list[slot];
    int row = g_off[e] + i;
    int t = ent >> 1;
    const float4* src = (const float4*)(x + (size_t)t * CI);
    float4* dst = (float4*)(g_xp + (size_t)row * CI);
#pragma unroll
    for (int j = lane; j < CI / 4; j += 32) {
        float4 v = src[j];
        v.x = tf32r(v.x); v.y = tf32r(v.y); v.z = tf32r(v.z); v.w = tf32r(v.w);
        dst[j] = v;
    }
    if (lane == 0) {
        g_rowof[ent] = row;
        g_wtp[row]   = g_wt[ent];
    }
}

// ---------------- HMMA grouped GEMM ------------------------------------------
// BM=128, BN=128, BK=32; 8 warps (2x4), warp tile 64x32 (4x4 m16n8k8)
// 2 CTAs/SM; 3-stage cp.async pipeline, single __syncthreads per k-iter.
#define BM 128
#define BN 128
#define BK 32
#define LDA 36                       // pad: (m*36+k)%32 = (4m+k)%32 conflict-free
#define LDB 132                      // pad: (k*132+n)%32 = (4k+n)%32 conflict-free
#define A_ST (BM * LDA)              // 4608 floats
#define B_ST (BK * LDB)              // 4224 floats
#define STG_FL (A_ST + B_ST)         // 8832 floats per stage
#define SMEM_SZ (3 * STG_FL * 4)     // 105984 bytes -> 2 CTAs/SM (212KB <= 228KB)

template<int KD, int ND, bool PH1>
__global__ __launch_bounds__(256, 2)
void k_mma(const float* __restrict__ bias) {
    extern __shared__ float sm[];
    const int e   = blockIdx.z;
    const int cnt = g_cnt[e];
    const int m0  = blockIdx.y * BM;
    if (m0 >= cnt) return;
    const int base = g_off[e];
    const int n0   = blockIdx.x * BN;
    const int tid  = threadIdx.x;
    const int lane = tid & 31;
    const int w    = tid >> 5;
    const int wm   = w >> 2, wn = w & 3;

    const float* Asrc = PH1 ? g_xp : g_hid;
    const float* Bsrc = (PH1 ? g_w1r : g_w2r) + (size_t)e * KD * ND;

    auto load_stage = [&](int kb, int buf) {
        float* as = sm + buf * STG_FL;
        float* bs = as + A_ST;
        const int k0 = kb * BK;
#pragma unroll
        for (int c = 0; c < 4; ++c) {                  // A: 128 x 32 fl
            int idx = tid + c * 256;
            int r = idx >> 3, q = idx & 7;
            int rr = m0 + r; rr = rr < cnt ? rr : cnt - 1;
            cp16(as + r * LDA + q * 4,
                 Asrc + (size_t)(base + rr) * KD + k0 + q * 4);
        }
#pragma unroll
        for (int c = 0; c < 4; ++c) {                  // B: 32 x 128 fl
            int idx = tid + c * 256;
            int k = idx >> 5, q = idx & 31;
            cp16(bs + k * LDB + q * 4,
                 Bsrc + (size_t)(k0 + k) * ND + n0 + q * 4);
        }
        cp_commit();
    };

    float acc[4][4][4];
#pragma unroll
    for (int mt = 0; mt < 4; ++mt)
#pragma unroll
        for (int nt = 0; nt < 4; ++nt)
#pragma unroll
            for (int j = 0; j < 4; ++j) acc[mt][nt][j] = 0.f;

    const int NK = KD / BK;
    load_stage(0, 0);
    load_stage(1, 1);
    int buf = 0, bufw = 2;                             // read / write rotors
    for (int kb = 0; kb < NK; ++kb) {
        cp_wait1();                                    // stage kb arrived (kb+1 in flight)
        __syncthreads();                               // all done reading buffer bufw
        if (kb + 2 < NK) load_stage(kb + 2, bufw);     // refill (kb-1)%3 early
        const float* as = sm + buf * STG_FL;
        const float* bs = as + A_ST;
        const float* pA = as + (wm * 64 + (lane >> 2)) * LDA + (lane & 3);
        const float* pB = bs + (lane & 3) * LDB + wn * 32 + (lane >> 2);
#pragma unroll
        for (int ks = 0; ks < 4; ++ks) {
            uint32_t af[4][4], bf[4][2];
#pragma unroll
            for (int mt = 0; mt < 4; ++mt) {
                af[mt][0] = __float_as_uint(pA[(mt * 16)     * LDA + ks * 8]);
                af[mt][1] = __float_as_uint(pA[(mt * 16 + 8) * LDA + ks * 8]);
                af[mt][2] = __float_as_uint(pA[(mt * 16)     * LDA + ks * 8 + 4]);
                af[mt][3] = __float_as_uint(pA[(mt * 16 + 8) * LDA + ks * 8 + 4]);
            }
#pragma unroll
            for (int nt = 0; nt < 4; ++nt) {
                bf[nt][0] = __float_as_uint(pB[(ks * 8)     * LDB + nt * 8]);
                bf[nt][1] = __float_as_uint(pB[(ks * 8 + 4) * LDB + nt * 8]);
            }
#pragma unroll
            for (int mt = 0; mt < 4; ++mt)
#pragma unroll
                for (int nt = 0; nt < 4; ++nt)
                    mma_tf32(acc[mt][nt], af[mt], bf[nt]);
        }
        buf  = (buf  == 2) ? 0 : buf  + 1;
        bufw = (bufw == 2) ? 0 : bufw + 1;
    }

    // ---- epilogue straight from registers ----
    const float* bp = bias + (size_t)e * ND + n0;
#pragma unroll
    for (int mt = 0; mt < 4; ++mt) {
        const int lr0 = wm * 64 + mt * 16 + (lane >> 2);
#pragma unroll
        for (int h = 0; h < 2; ++h) {
            const int lr = lr0 + h * 8;
            if (m0 + lr >= cnt) continue;
            const int grow = base + m0 + lr;
            const float wt = PH1 ? 0.f : g_wtp[grow];
#pragma unroll
            for (int nt = 0; nt < 4; ++nt) {
                const int col = wn * 32 + nt * 8 + (lane & 3) * 2;
                float v0 = acc[mt][nt][h * 2 + 0] + bp[col];
                float v1 = acc[mt][nt][h * 2 + 1] + bp[col + 1];
                if (PH1) {
                    v0 = tf32r(0.5f * v0 * (1.f + erff(v0 * 0.70710678118654752f)));
                    v1 = tf32r(0.5f * v1 * (1.f + erff(v1 * 0.70710678118654752f)));
                    float2 o = make_float2(v0, v1);
                    *(float2*)&g_hid[(size_t)grow * NH + n0 + col] = o;
                } else {
                    float2 o = make_float2(wt * v0, wt * v1);
                    *(float2*)&g_tmp[(size_t)grow * CO + n0 + col] = o;
                }
            }
        }
    }
}

// ---------------- combine ----------------------------------------------------
__global__ void k_combine(float* __restrict__ out) {
    int i = blockIdx.x * 256 + threadIdx.x;
    const int tot = NT * CO / 4;
    if (i >= tot) return;
    int t = i / (CO / 4), c = i % (CO / 4);
    int r0 = g_rowof[2 * t], r1 = g_rowof[2 * t + 1];
    const float4* tp = (const float4*)g_tmp;
    float4 u = tp[(size_t)r0 * (CO / 4) + c];
    float4 v = tp[(size_t)r1 * (CO / 4) + c];
    float4 r; r.x = u.x + v.x; r.y = u.y + v.y; r.z = u.z + v.z; r.w = u.w + v.w;
    ((float4*)out)[i] = r;
}

// ---------------- launch -----------------------------------------------------
extern "C" void kernel_launch(void* const* d_in, const int* in_sizes, int n_in,
                              void* d_out, int out_size) {
    const float* x  = (const float*)d_in[0];
    const float* Wg = (const float*)d_in[1];
    const float* bg = (const float*)d_in[2];
    const float* eb = (const float*)d_in[3];
    const float* W1 = (const float*)d_in[4];
    const float* b1 = (const float*)d_in[5];
    const float* W2 = (const float*)d_in[6];
    const float* b2 = (const float*)d_in[7];
    float* out = (float*)d_out;

    cudaFuncSetAttribute(k_mma<CI, NH, true >, cudaFuncAttributeMaxDynamicSharedMemorySize, SMEM_SZ);
    cudaFuncSetAttribute(k_mma<NH, CO, false>, cudaFuncAttributeMaxDynamicSharedMemorySize, SMEM_SZ);

    const int roundw_blocks = (NE * CI * NH / 4 + NE * NH * CO / 4) / 256;  // 2048
    k_zero<<<1, 32>>>();
    k_gate_roundw<<<NT / 8 + roundw_blocks, 256>>>(x, Wg, bg, eb, W1, W2);
    k_sched<<<1, 32>>>();
    k_permute<<<NE * NT / 8, 256>>>(x);

    k_mma<CI, NH, true ><<<dim3(NH / 128, 64, NE), 256, SMEM_SZ>>>(b1);
    k_mma<NH, CO, false><<<dim3(CO / 128, 64, NE), 256, SMEM_SZ>>>(b2);

    k_combine<<<(NT * CO / 4 + 255) / 256, 256>>>(out);
}